// round 14
// baseline (speedup 1.0000x reference)
#include <cuda_runtime.h>
#include <cstdint>

#define BATCH   2048
#define NCLS    50257
#define KPOS    20
#define THREADS 256
#define QPR     4                    // quarters per row
#define QF4     3141                 // float4 per quarter (4*3141 >= max n4 12564)
#define GRID    (BATCH * QPR)        // 8192 CTAs

// Scratch (device globals => allocation-free)
__device__ float g_q[GRID];          // per-quarter partial sums (log2 domain)
__device__ float g_a[BATCH];         // per-row: pos/K - w*corr
__device__ float g_w[BATCH];         // per-row: 1/(NCLS - uniq)
__device__ int   g_ticket;

__device__ __forceinline__ float ex2f(float x) {
    float r; asm("ex2.approx.ftz.f32 %0, %1;" : "=f"(r) : "f"(x)); return r;
}
__device__ __forceinline__ float lg2f(float x) {
    float r; asm("lg2.approx.ftz.f32 %0, %1;" : "=f"(r) : "f"(x)); return r;
}

#define L2E 1.4426950408889634f
#define LN2 0.6931471805599453f

// log(sigmoid(z)) = -ln2 * log2(1 + 2^(-z*log2e))  (inputs ~N(0,1))
__device__ __forceinline__ float log_sig(float z) {
    return -LN2 * lg2f(1.0f + ex2f(-z * L2E));
}

// product of (1 + 2^(x_i * log2e)) over a float4
__device__ __forceinline__ float prod4(float4 v) {
    float t0 = ex2f(v.x * L2E);
    float t1 = ex2f(v.y * L2E);
    float t2 = ex2f(v.z * L2E);
    float t3 = ex2f(v.w * L2E);
    return ((1.0f + t0) * (1.0f + t1)) * ((1.0f + t2) * (1.0f + t3));
}

__global__ __launch_bounds__(THREADS, 8) void mlsml_kernel(
    const float* __restrict__ x,    // [BATCH, NCLS]
    const int*   __restrict__ tgt,  // [BATCH, KPOS]
    float*       __restrict__ out)  // [1]
{
    const int bid = blockIdx.x;
    const int row = bid >> 2;
    const int q   = bid & 3;
    const int tid = threadIdx.x;
    const float* __restrict__ xr = x + (size_t)row * NCLS;

    // Row base offset mod 4 == row mod 4 (50257 % 4 == 1) -> peel to 16B align.
    const int head = (4 - (row & 3)) & 3;
    const int n4   = (NCLS - head) >> 2;
    const int rem  = (NCLS - head) & 3;

    // s2: partial sum of log2(1 + exp(x)) for this quarter (log2 domain)
    float s2 = 0.0f;
    if (q == 0 && tid < head)
        s2 += lg2f(1.0f + ex2f(xr[tid] * L2E));
    if (q == QPR - 1 && tid < rem)
        s2 += lg2f(1.0f + ex2f(xr[head + 4 * n4 + tid] * L2E));

    const int lo = q * QF4;
    const int hi = min(n4, lo + QF4);
    const float4* __restrict__ p = (const float4*)(xr + head);

    int i = lo + tid;
    // Unroll-4: 4 independent LDG.128 (16 data regs, fits 32-reg budget);
    // one lg2 per 8 elements (8-term products stay inside fp32 range).
    for (; i + 3 * THREADS < hi; i += 4 * THREADS) {
        float4 v0 = __ldcs(p + i);
        float4 v1 = __ldcs(p + i + 1 * THREADS);
        float4 v2 = __ldcs(p + i + 2 * THREADS);
        float4 v3 = __ldcs(p + i + 3 * THREADS);
        s2 += lg2f(prod4(v0) * prod4(v1));
        s2 += lg2f(prod4(v2) * prod4(v3));
    }
    for (; i < hi; i += THREADS) {
        float4 v = __ldcs(p + i);
        s2 += lg2f(prod4(v));
    }

    // Block reduction of s2
    #pragma unroll
    for (int o = 16; o > 0; o >>= 1)
        s2 += __shfl_down_sync(0xffffffffu, s2, o);

    __shared__ float red[THREADS / 32];
    __shared__ int   sIsLast;
    const int lane = tid & 31, wid = tid >> 5;
    if (lane == 0) red[wid] = s2;
    __syncthreads();

    if (wid == 0) {
        float S2 = (lane < THREADS / 32) ? red[lane] : 0.0f;
        #pragma unroll
        for (int o = 4; o > 0; o >>= 1)
            S2 += __shfl_down_sync(0xffffffffu, S2, o);
        if (lane == 0) g_q[bid] = S2;

        // Quarter 0 also computes the row target epilogue (warp-parallel K=20)
        if (q == 0) {
            float pos = 0.0f, corr = 0.0f;
            int   uq  = 0;
            if (lane < KPOS) {
                int   idx = __ldg(tgt + row * KPOS + lane);
                float v   = __ldg(xr + idx);
                pos = log_sig(v);
                unsigned m = __match_any_sync(0x000FFFFFu, idx);
                if ((m & (unsigned)(-(int)m)) == (1u << lane)) {
                    corr = log_sig(-v);
                    uq   = 1;
                }
            }
            #pragma unroll
            for (int o = 16; o > 0; o >>= 1) {
                pos  += __shfl_down_sync(0xffffffffu, pos,  o);
                corr += __shfl_down_sync(0xffffffffu, corr, o);
                uq   += __shfl_down_sync(0xffffffffu, uq,   o);
            }
            if (lane == 0) {
                float w = 1.0f / (float)(NCLS - uq);
                g_w[row] = w;
                g_a[row] = pos * (1.0f / KPOS) - corr * w;
            }
        }

        if (lane == 0) {
            __threadfence();
            int ticket = atomicAdd(&g_ticket, 1);
            sIsLast = (ticket == GRID - 1);
        }
    }
    __syncthreads();

    // Last CTA: deterministic fixed-order per-row reassembly + final mean
    if (sIsLast) {
        __threadfence();
        float acc = 0.0f;
        for (int r = tid; r < BATCH; r += THREADS) {
            float ss = (__ldcg(&g_q[4 * r + 0]) + __ldcg(&g_q[4 * r + 1])) +
                       (__ldcg(&g_q[4 * r + 2]) + __ldcg(&g_q[4 * r + 3]));
            float S = -LN2 * ss;   // sum log_sigmoid(-x) over row r
            acc += __ldcg(&g_a[r]) + __ldcg(&g_w[r]) * S;
        }
        #pragma unroll
        for (int o = 16; o > 0; o >>= 1)
            acc += __shfl_down_sync(0xffffffffu, acc, o);
        if (lane == 0) red[wid] = acc;
        __syncthreads();
        if (tid == 0) {
            float S = 0.0f;
            #pragma unroll
            for (int w = 0; w < THREADS / 32; w++) S += red[w];
            out[0] = -S / (float)BATCH;
            g_ticket = 0;  // reset for next graph replay
        }
    }
}

extern "C" void kernel_launch(void* const* d_in, const int* in_sizes, int n_in,
                              void* d_out, int out_size) {
    const float* x   = (const float*)d_in[0];
    const int*   tgt = (const int*)d_in[1];
    float*       out = (float*)d_out;
    mlsml_kernel<<<GRID, THREADS>>>(x, tgt, out);
}

// round 15
// speedup vs baseline: 1.0060x; 1.0060x over previous
#include <cuda_runtime.h>
#include <cstdint>

#define BATCH   2048
#define NCLS    50257
#define KPOS    20
#define THREADS 256
#define QPR     4                    // quarters per row
#define QF4     3141                 // float4 per quarter (4*3141 >= max n4 12564)
#define GRID    (BATCH * QPR)        // 8192 CTAs

// Scratch (device globals => allocation-free)
__device__ float g_q[GRID];          // per-quarter partial sums (log2 domain)
__device__ float g_a[BATCH];         // per-row: pos/K - w*corr
__device__ float g_w[BATCH];         // per-row: 1/(NCLS - uniq)
__device__ int   g_ticket;

__device__ __forceinline__ float ex2f(float x) {
    float r; asm("ex2.approx.ftz.f32 %0, %1;" : "=f"(r) : "f"(x)); return r;
}
__device__ __forceinline__ float lg2f(float x) {
    float r; asm("lg2.approx.ftz.f32 %0, %1;" : "=f"(r) : "f"(x)); return r;
}

#define L2E 1.4426950408889634f
#define LN2 0.6931471805599453f

// log(sigmoid(z)) = -ln2 * log2(1 + 2^(-z*log2e))  (inputs ~N(0,1))
__device__ __forceinline__ float log_sig(float z) {
    return -LN2 * lg2f(1.0f + ex2f(-z * L2E));
}

// product of (1 + 2^(x_i * log2e)) over a float4
__device__ __forceinline__ float prod4(float4 v) {
    float t0 = ex2f(v.x * L2E);
    float t1 = ex2f(v.y * L2E);
    float t2 = ex2f(v.z * L2E);
    float t3 = ex2f(v.w * L2E);
    return ((1.0f + t0) * (1.0f + t1)) * ((1.0f + t2) * (1.0f + t3));
}

__global__ __launch_bounds__(THREADS, 8) void mlsml_kernel(
    const float* __restrict__ x,    // [BATCH, NCLS]
    const int*   __restrict__ tgt,  // [BATCH, KPOS]
    float*       __restrict__ out)  // [1]
{
    const int bid = blockIdx.x;
    const int row = bid >> 2;
    const int q   = bid & 3;
    const int tid = threadIdx.x;
    const float* __restrict__ xr = x + (size_t)row * NCLS;

    // Row base offset mod 4 == row mod 4 (50257 % 4 == 1) -> peel to 16B align.
    const int head = (4 - (row & 3)) & 3;
    const int n4   = (NCLS - head) >> 2;
    const int rem  = (NCLS - head) & 3;

    // s2: partial sum of log2(1 + exp(x)) for this quarter (log2 domain)
    float s2 = 0.0f;
    if (q == 0 && tid < head)
        s2 += lg2f(1.0f + ex2f(xr[tid] * L2E));
    if (q == QPR - 1 && tid < rem)
        s2 += lg2f(1.0f + ex2f(xr[head + 4 * n4 + tid] * L2E));

    const int lo = q * QF4;
    const int hi = min(n4, lo + QF4);
    const float4* __restrict__ p = (const float4*)(xr + head);

    int i = lo + tid;
    // Unroll-4: 4 independent LDG.128 (16 data regs, fits 32-reg budget);
    // one lg2 per 8 elements (8-term products stay inside fp32 range).
    for (; i + 3 * THREADS < hi; i += 4 * THREADS) {
        float4 v0 = __ldcs(p + i);
        float4 v1 = __ldcs(p + i + 1 * THREADS);
        float4 v2 = __ldcs(p + i + 2 * THREADS);
        float4 v3 = __ldcs(p + i + 3 * THREADS);
        s2 += lg2f(prod4(v0) * prod4(v1));
        s2 += lg2f(prod4(v2) * prod4(v3));
    }
    for (; i < hi; i += THREADS) {
        float4 v = __ldcs(p + i);
        s2 += lg2f(prod4(v));
    }

    // Block reduction of s2
    #pragma unroll
    for (int o = 16; o > 0; o >>= 1)
        s2 += __shfl_down_sync(0xffffffffu, s2, o);

    __shared__ float red[THREADS / 32];
    __shared__ int   sIsLast;
    const int lane = tid & 31, wid = tid >> 5;
    if (lane == 0) red[wid] = s2;
    __syncthreads();

    if (wid == 0) {
        float S2 = (lane < THREADS / 32) ? red[lane] : 0.0f;
        #pragma unroll
        for (int o = 4; o > 0; o >>= 1)
            S2 += __shfl_down_sync(0xffffffffu, S2, o);
        if (lane == 0) g_q[bid] = S2;

        // Quarter 0 also computes the row target epilogue (warp-parallel K=20)
        if (q == 0) {
            float pos = 0.0f, corr = 0.0f;
            int   uq  = 0;
            if (lane < KPOS) {
                int   idx = __ldg(tgt + row * KPOS + lane);
                float v   = __ldg(xr + idx);
                pos = log_sig(v);
                unsigned m = __match_any_sync(0x000FFFFFu, idx);
                if ((m & (unsigned)(-(int)m)) == (1u << lane)) {
                    corr = log_sig(-v);
                    uq   = 1;
                }
            }
            #pragma unroll
            for (int o = 16; o > 0; o >>= 1) {
                pos  += __shfl_down_sync(0xffffffffu, pos,  o);
                corr += __shfl_down_sync(0xffffffffu, corr, o);
                uq   += __shfl_down_sync(0xffffffffu, uq,   o);
            }
            if (lane == 0) {
                float w = 1.0f / (float)(NCLS - uq);
                g_w[row] = w;
                g_a[row] = pos * (1.0f / KPOS) - corr * w;
            }
        }

        if (lane == 0) {
            __threadfence();
            int ticket = atomicAdd(&g_ticket, 1);
            sIsLast = (ticket == GRID - 1);
        }
    }
    __syncthreads();

    // Last CTA: deterministic fixed-order per-row reassembly + final mean
    if (sIsLast) {
        __threadfence();
        float acc = 0.0f;
        for (int r = tid; r < BATCH; r += THREADS) {
            float ss = (__ldcg(&g_q[4 * r + 0]) + __ldcg(&g_q[4 * r + 1])) +
                       (__ldcg(&g_q[4 * r + 2]) + __ldcg(&g_q[4 * r + 3]));
            float S = -LN2 * ss;   // sum log_sigmoid(-x) over row r
            acc += __ldcg(&g_a[r]) + __ldcg(&g_w[r]) * S;
        }
        #pragma unroll
        for (int o = 16; o > 0; o >>= 1)
            acc += __shfl_down_sync(0xffffffffu, acc, o);
        if (lane == 0) red[wid] = acc;
        __syncthreads();
        if (tid == 0) {
            float S = 0.0f;
            #pragma unroll
            for (int w = 0; w < THREADS / 32; w++) S += red[w];
            out[0] = -S / (float)BATCH;
            g_ticket = 0;  // reset for next graph replay
        }
    }
}

extern "C" void kernel_launch(void* const* d_in, const int* in_sizes, int n_in,
                              void* d_out, int out_size) {
    const float* x   = (const float*)d_in[0];
    const int*   tgt = (const int*)d_in[1];
    float*       out = (float*)d_out;
    mlsml_kernel<<<GRID, THREADS>>>(x, tgt, out);
}

// round 16
// speedup vs baseline: 1.0547x; 1.0484x over previous
#include <cuda_runtime.h>
#include <cstdint>

#define BATCH   2048
#define NCLS    50257
#define KPOS    20
#define THREADS 256
#define QPR     4                    // quarters per row
#define QF4     3141                 // float4 per quarter (4*3141 >= max n4 12564)
#define GRID    (BATCH * QPR)        // 8192 CTAs

// Scratch (device globals => allocation-free)
__device__ __align__(16) float g_q[GRID];   // per-quarter partials (log2 domain), float4/row
__device__ float g_a[BATCH];         // per-row: pos/K - w*corr
__device__ float g_w[BATCH];         // per-row: 1/(NCLS - uniq)
__device__ int   g_ticket;

__device__ __forceinline__ float ex2f(float x) {
    float r; asm("ex2.approx.ftz.f32 %0, %1;" : "=f"(r) : "f"(x)); return r;
}
__device__ __forceinline__ float lg2f(float x) {
    float r; asm("lg2.approx.ftz.f32 %0, %1;" : "=f"(r) : "f"(x)); return r;
}

#define L2E 1.4426950408889634f
#define LN2 0.6931471805599453f

// log(sigmoid(z)) = -ln2 * log2(1 + 2^(-z*log2e))  (inputs ~N(0,1))
__device__ __forceinline__ float log_sig(float z) {
    return -LN2 * lg2f(1.0f + ex2f(-z * L2E));
}

// product of (1 + 2^(x_i * log2e)) over a float4
__device__ __forceinline__ float prod4(float4 v) {
    float t0 = ex2f(v.x * L2E);
    float t1 = ex2f(v.y * L2E);
    float t2 = ex2f(v.z * L2E);
    float t3 = ex2f(v.w * L2E);
    return ((1.0f + t0) * (1.0f + t1)) * ((1.0f + t2) * (1.0f + t3));
}

__global__ __launch_bounds__(THREADS, 8) void mlsml_kernel(
    const float* __restrict__ x,    // [BATCH, NCLS]
    const int*   __restrict__ tgt,  // [BATCH, KPOS]
    float*       __restrict__ out)  // [1]
{
    const int bid = blockIdx.x;
    const int row = bid >> 2;
    const int q   = bid & 3;
    const int tid = threadIdx.x;
    const float* __restrict__ xr = x + (size_t)row * NCLS;

    // Row base offset mod 4 == row mod 4 (50257 % 4 == 1) -> peel to 16B align.
    const int head = (4 - (row & 3)) & 3;
    const int n4   = (NCLS - head) >> 2;
    const int rem  = (NCLS - head) & 3;

    // s2: partial sum of log2(1 + exp(x)) for this quarter (log2 domain)
    float s2 = 0.0f;
    if (q == 0 && tid < head)
        s2 += lg2f(1.0f + ex2f(xr[tid] * L2E));
    if (q == QPR - 1 && tid < rem)
        s2 += lg2f(1.0f + ex2f(xr[head + 4 * n4 + tid] * L2E));

    const int lo = q * QF4;
    const int hi = min(n4, lo + QF4);
    const float4* __restrict__ p = (const float4*)(xr + head);

    int i = lo + tid;
    // Unroll-4: 4 independent LDG.128 (16 data regs, fits 32-reg budget);
    // one lg2 per 8 elements (8-term products stay inside fp32 range).
    for (; i + 3 * THREADS < hi; i += 4 * THREADS) {
        float4 v0 = __ldcs(p + i);
        float4 v1 = __ldcs(p + i + 1 * THREADS);
        float4 v2 = __ldcs(p + i + 2 * THREADS);
        float4 v3 = __ldcs(p + i + 3 * THREADS);
        s2 += lg2f(prod4(v0) * prod4(v1));
        s2 += lg2f(prod4(v2) * prod4(v3));
    }
    for (; i < hi; i += THREADS) {
        float4 v = __ldcs(p + i);
        s2 += lg2f(prod4(v));
    }

    // Block reduction of s2
    #pragma unroll
    for (int o = 16; o > 0; o >>= 1)
        s2 += __shfl_down_sync(0xffffffffu, s2, o);

    __shared__ float red[THREADS / 32];
    __shared__ int   sIsLast;
    const int lane = tid & 31, wid = tid >> 5;
    if (lane == 0) red[wid] = s2;
    __syncthreads();

    if (wid == 0) {
        float S2 = (lane < THREADS / 32) ? red[lane] : 0.0f;
        #pragma unroll
        for (int o = 4; o > 0; o >>= 1)
            S2 += __shfl_down_sync(0xffffffffu, S2, o);
        if (lane == 0) g_q[bid] = S2;

        // Quarter 0 also computes the row target epilogue (warp-parallel K=20)
        if (q == 0) {
            float pos = 0.0f, corr = 0.0f;
            int   uq  = 0;
            if (lane < KPOS) {
                int   idx = __ldg(tgt + row * KPOS + lane);
                float v   = __ldg(xr + idx);
                pos = log_sig(v);
                unsigned m = __match_any_sync(0x000FFFFFu, idx);
                if ((m & (unsigned)(-(int)m)) == (1u << lane)) {
                    corr = log_sig(-v);
                    uq   = 1;
                }
            }
            #pragma unroll
            for (int o = 16; o > 0; o >>= 1) {
                pos  += __shfl_down_sync(0xffffffffu, pos,  o);
                corr += __shfl_down_sync(0xffffffffu, corr, o);
                uq   += __shfl_down_sync(0xffffffffu, uq,   o);
            }
            if (lane == 0) {
                float w = 1.0f / (float)(NCLS - uq);
                g_w[row] = w;
                g_a[row] = pos * (1.0f / KPOS) - corr * w;
            }
        }

        if (lane == 0) {
            __threadfence();
            int ticket = atomicAdd(&g_ticket, 1);
            sIsLast = (ticket == GRID - 1);
        }
    }
    __syncthreads();

    // Last CTA: deterministic fixed-order per-row reassembly + final mean.
    // g_q is 16B-aligned: one LDG.128 per row instead of 4 scalar loads.
    if (sIsLast) {
        __threadfence();
        const float4* __restrict__ q4 = (const float4*)g_q;
        float acc = 0.0f;
        #pragma unroll
        for (int k = 0; k < BATCH / THREADS; k++) {
            int r = tid + k * THREADS;
            float4 v = __ldcg(&q4[r]);
            float  a = __ldcg(&g_a[r]);
            float  w = __ldcg(&g_w[r]);
            float ss = (v.x + v.y) + (v.z + v.w);
            acc += a + w * (-LN2 * ss);
        }
        #pragma unroll
        for (int o = 16; o > 0; o >>= 1)
            acc += __shfl_down_sync(0xffffffffu, acc, o);
        if (lane == 0) red[wid] = acc;
        __syncthreads();
        if (tid == 0) {
            float S = 0.0f;
            #pragma unroll
            for (int w = 0; w < THREADS / 32; w++) S += red[w];
            out[0] = -S / (float)BATCH;
            g_ticket = 0;  // reset for next graph replay
        }
    }
}

extern "C" void kernel_launch(void* const* d_in, const int* in_sizes, int n_in,
                              void* d_out, int out_size) {
    const float* x   = (const float*)d_in[0];
    const int*   tgt = (const int*)d_in[1];
    float*       out = (float*)d_out;
    mlsml_kernel<<<GRID, THREADS>>>(x, tgt, out);
}